// round 1
// baseline (speedup 1.0000x reference)
#include <cuda_runtime.h>

#define NN 50000
#define HD 128

typedef unsigned long long u64;

// ---------------- scratch (static device globals; no allocation) ----------------
__device__ __align__(16) float g_deg[NN];                  // deg -> dinv (in place)
__device__ __align__(16) float g_xw[(size_t)NN * 128];     // xw / cpre
__device__ __align__(16) float g_agg[(size_t)NN * 128];    // aggregation buffer
__device__ __align__(16) float g_h1[(size_t)NN * 128];     // relu output layer 1
__device__ __align__(16) float g_comb[(size_t)NN * 256];   // [emb | h] then [emb | r*h]
__device__ __align__(16) float g_zr[(size_t)NN * 256];     // [z_pre | r_pre]
__device__ __align__(16) float g_wzr[256 * 256];           // [W_z | W_r]

// ---------------- fp32x2 packed-FMA helpers (Blackwell FFMA2 pipe) ----------------
__device__ __forceinline__ u64 pack2(float x, float y) {
    u64 r; asm("mov.b64 %0, {%1, %2};" : "=l"(r) : "f"(x), "f"(y)); return r;
}
__device__ __forceinline__ void fma2(u64 &d, u64 a, u64 b) {
    asm("fma.rn.f32x2 %0, %1, %2, %3;" : "=l"(d) : "l"(a), "l"(b), "l"(d));
}
__device__ __forceinline__ float2 unpack2(u64 v) {
    float2 r; asm("mov.b64 {%0, %1}, %2;" : "=f"(r.x), "=f"(r.y) : "l"(v)); return r;
}

__device__ __forceinline__ float sigmoidf_(float x) { return 1.0f / (1.0f + __expf(-x)); }

// ---------------- degree / dinv ----------------
__global__ void k_init_deg() {
    int i = blockIdx.x * blockDim.x + threadIdx.x;
    if (i < NN) g_deg[i] = 1.0f;   // self loop
}
__global__ void k_deg_atomic(const int* __restrict__ dst, int E) {
    int i = blockIdx.x * blockDim.x + threadIdx.x;
    if (i < E) atomicAdd(&g_deg[dst[i]], 1.0f);
}
__global__ void k_dinv() {
    int i = blockIdx.x * blockDim.x + threadIdx.x;
    if (i < NN) g_deg[i] = rsqrtf(g_deg[i]);
}

// ---------------- GEMM: C[M,Nc] = A[M,K] @ B[K,Nc]; tiles 64x128, fp32x2 FMA ----------------
__global__ __launch_bounds__(256) void k_gemm(
    const float* __restrict__ A, const float* __restrict__ B, float* __restrict__ C,
    int M, int K, int Nc, int ldc)
{
    __shared__ float As[64][33];       // padded: compute reads 2-way max
    __shared__ float Bs[32][128];

    int bm = blockIdx.x * 64;
    int bn = blockIdx.y * 128;
    int tid = threadIdx.x;
    int tm = tid >> 4;   // 0..15
    int tn = tid & 15;   // 0..15

    u64 acc[4][4];
#pragma unroll
    for (int m = 0; m < 4; m++)
#pragma unroll
        for (int n = 0; n < 4; n++) acc[m][n] = 0ULL;

    for (int k0 = 0; k0 < K; k0 += 32) {
        // load A tile: 64 rows x 32 cols
#pragma unroll
        for (int i = 0; i < 2; i++) {
            int idx = tid + i * 256;
            int row = idx >> 3;
            int c4  = (idx & 7) << 2;
            float4 v = make_float4(0.f, 0.f, 0.f, 0.f);
            int gr = bm + row;
            if (gr < M) v = *(const float4*)&A[(size_t)gr * K + k0 + c4];
            As[row][c4 + 0] = v.x; As[row][c4 + 1] = v.y;
            As[row][c4 + 2] = v.z; As[row][c4 + 3] = v.w;
        }
        // load B tile: 32 rows x 128 cols
#pragma unroll
        for (int i = 0; i < 4; i++) {
            int idx = tid + i * 256;
            int row = idx >> 5;
            int c4  = (idx & 31) << 2;
            *(float4*)&Bs[row][c4] = *(const float4*)&B[(size_t)(k0 + row) * Nc + bn + c4];
        }
        __syncthreads();

#pragma unroll
        for (int kk = 0; kk < 32; kk++) {
            ulonglong2 b01 = *(const ulonglong2*)&Bs[kk][tn * 8];
            ulonglong2 b23 = *(const ulonglong2*)&Bs[kk][tn * 8 + 4];
#pragma unroll
            for (int m = 0; m < 4; m++) {
                float a = As[tm * 4 + m][kk];
                u64 aa = pack2(a, a);
                fma2(acc[m][0], aa, b01.x);
                fma2(acc[m][1], aa, b01.y);
                fma2(acc[m][2], aa, b23.x);
                fma2(acc[m][3], aa, b23.y);
            }
        }
        __syncthreads();
    }

#pragma unroll
    for (int m = 0; m < 4; m++) {
        int gr = bm + tm * 4 + m;
        if (gr >= M) continue;
        float2 o0 = unpack2(acc[m][0]);
        float2 o1 = unpack2(acc[m][1]);
        float2 o2 = unpack2(acc[m][2]);
        float2 o3 = unpack2(acc[m][3]);
        size_t base = (size_t)gr * ldc + bn + tn * 8;
        *(float4*)&C[base]     = make_float4(o0.x, o0.y, o1.x, o1.y);
        *(float4*)&C[base + 4] = make_float4(o2.x, o2.y, o3.x, o3.y);
    }
}

// ---------------- aggregation ----------------
// agg = xw * dinv^2 (self loop term)
__global__ void k_selfloop() {
    int i = blockIdx.x * blockDim.x + threadIdx.x;   // over NN*32 float4 units
    if (i >= NN * 32) return;
    int node = i >> 5;
    float dv = g_deg[node];
    float c = dv * dv;
    float4 v = ((const float4*)g_xw)[i];
    v.x *= c; v.y *= c; v.z *= c; v.w *= c;
    ((float4*)g_agg)[i] = v;
}

// one warp per edge; vector reduction into agg[dst]
__global__ void k_edge_agg(const int* __restrict__ edge, int E) {
    int t = blockIdx.x * blockDim.x + threadIdx.x;
    int e = t >> 5;
    int lane = t & 31;
    if (e >= E) return;
    int s = edge[e];
    int d = edge[E + e];
    float c = g_deg[s] * g_deg[d];
    float4 v = ((const float4*)g_xw)[s * 32 + lane];
    v.x *= c; v.y *= c; v.z *= c; v.w *= c;
    float* p = &g_agg[(size_t)d * 128 + lane * 4];
    asm volatile("red.global.add.v4.f32 [%0], {%1, %2, %3, %4};"
                 :: "l"(p), "f"(v.x), "f"(v.y), "f"(v.z), "f"(v.w) : "memory");
}

// h1 = relu(agg + b_in)
__global__ void k_relu_bias(const float* __restrict__ b) {
    int i = blockIdx.x * blockDim.x + threadIdx.x;
    if (i >= NN * 32) return;
    int c4 = (i & 31) << 2;
    float4 v = ((const float4*)g_agg)[i];
    float4 bb = *(const float4*)&b[c4];
    v.x = fmaxf(v.x + bb.x, 0.f); v.y = fmaxf(v.y + bb.y, 0.f);
    v.z = fmaxf(v.z + bb.z, 0.f); v.w = fmaxf(v.w + bb.w, 0.f);
    ((float4*)g_h1)[i] = v;
}

// emb = agg + b_hid; comb = [emb | h]
__global__ void k_emb_comb(const float* __restrict__ b, const float* __restrict__ h) {
    int i = blockIdx.x * blockDim.x + threadIdx.x;
    if (i >= NN * 32) return;
    int node = i >> 5;
    int c4 = i & 31;
    float4 v = ((const float4*)g_agg)[i];
    float4 bb = *(const float4*)&b[c4 << 2];
    v.x += bb.x; v.y += bb.y; v.z += bb.z; v.w += bb.w;
    ((float4*)g_comb)[node * 64 + c4] = v;
    ((float4*)g_comb)[node * 64 + 32 + c4] = ((const float4*)h)[i];
}

// Wzr[k][j] = j<128 ? W_z[k][j] : W_r[k][j-128]
__global__ void k_build_wzr(const float* __restrict__ Wz, const float* __restrict__ Wr) {
    int k = blockIdx.x;
    int j = threadIdx.x;
    g_wzr[k * 256 + j]       = Wz[k * 128 + j];
    g_wzr[k * 256 + 128 + j] = Wr[k * 128 + j];
}

// comb[:,128:] = sigmoid(zr[:,128:]+b_r) * h
__global__ void k_rh(const float* __restrict__ br, const float* __restrict__ h) {
    int i = blockIdx.x * blockDim.x + threadIdx.x;
    if (i >= NN * 32) return;
    int node = i >> 5;
    int c4 = i & 31;
    float4 z = ((const float4*)g_zr)[node * 64 + 32 + c4];
    float4 bb = *(const float4*)&br[c4 << 2];
    float4 hv = ((const float4*)h)[i];
    float4 r;
    r.x = sigmoidf_(z.x + bb.x) * hv.x;
    r.y = sigmoidf_(z.y + bb.y) * hv.y;
    r.z = sigmoidf_(z.z + bb.z) * hv.z;
    r.w = sigmoidf_(z.w + bb.w) * hv.w;
    ((float4*)g_comb)[node * 64 + 32 + c4] = r;
}

// out = (1-u)*h + u*tanh(cpre + b_c), u = sigmoid(zr[:, :128] + b_z)
__global__ void k_final(const float* __restrict__ bz, const float* __restrict__ bc,
                        const float* __restrict__ h, float* __restrict__ out) {
    int i = blockIdx.x * blockDim.x + threadIdx.x;
    if (i >= NN * 32) return;
    int node = i >> 5;
    int c4 = i & 31;
    float4 zp = ((const float4*)g_zr)[node * 64 + c4];
    float4 cp = ((const float4*)g_xw)[i];
    float4 vbz = *(const float4*)&bz[c4 << 2];
    float4 vbc = *(const float4*)&bc[c4 << 2];
    float4 hv = ((const float4*)h)[i];
    float4 o;
    {
        float u = sigmoidf_(zp.x + vbz.x); float c = tanhf(cp.x + vbc.x);
        o.x = (1.f - u) * hv.x + u * c;
    }
    {
        float u = sigmoidf_(zp.y + vbz.y); float c = tanhf(cp.y + vbc.y);
        o.y = (1.f - u) * hv.y + u * c;
    }
    {
        float u = sigmoidf_(zp.z + vbz.z); float c = tanhf(cp.z + vbc.z);
        o.z = (1.f - u) * hv.z + u * c;
    }
    {
        float u = sigmoidf_(zp.w + vbz.w); float c = tanhf(cp.w + vbc.w);
        o.w = (1.f - u) * hv.w + u * c;
    }
    ((float4*)out)[i] = o;
}

// ---------------- launcher ----------------
extern "C" void kernel_launch(void* const* d_in, const int* in_sizes, int n_in,
                              void* d_out, int out_size) {
    const float* x     = (const float*)d_in[0];
    const float* h     = (const float*)d_in[1];
    const int*   edge  = (const int*)d_in[2];
    const float* W_in  = (const float*)d_in[3];
    const float* b_in  = (const float*)d_in[4];
    const float* W_hid = (const float*)d_in[5];
    const float* b_hid = (const float*)d_in[6];
    const float* W_z   = (const float*)d_in[7];
    const float* b_z   = (const float*)d_in[8];
    const float* W_r   = (const float*)d_in[9];
    const float* b_r   = (const float*)d_in[10];
    const float* W_c   = (const float*)d_in[11];
    const float* b_c   = (const float*)d_in[12];
    float* out = (float*)d_out;

    const int N = in_sizes[0] / 128;   // 50000
    const int E = in_sizes[2] / 2;     // 600000

    float *p_xw, *p_h1, *p_comb, *p_zr, *p_wzr;
    cudaGetSymbolAddress((void**)&p_xw,   g_xw);
    cudaGetSymbolAddress((void**)&p_h1,   g_h1);
    cudaGetSymbolAddress((void**)&p_comb, g_comb);
    cudaGetSymbolAddress((void**)&p_zr,   g_zr);
    cudaGetSymbolAddress((void**)&p_wzr,  g_wzr);

    const int T = 256;
    const int nv4 = NN * 32;                 // float4 units per [N,128] tensor
    const int gEw = (E * 32 + T - 1) / T;    // one warp per edge
    dim3 g1((N + 63) / 64, 1);
    dim3 g2((N + 63) / 64, 2);

    // degree -> dinv
    k_init_deg<<<(NN + T - 1) / T, T>>>();
    k_deg_atomic<<<(E + T - 1) / T, T>>>(edge + E, E);
    k_dinv<<<(NN + T - 1) / T, T>>>();

    // layer 1: h1 = relu(GCN(x, W_in) + b_in)
    k_gemm<<<g1, T>>>(x, W_in, p_xw, N, 128, 128, 128);
    k_selfloop<<<(nv4 + T - 1) / T, T>>>();
    k_edge_agg<<<gEw, T>>>(edge, E);
    k_relu_bias<<<(nv4 + T - 1) / T, T>>>(b_in);

    // layer 2: emb = GCN(h1, W_hid) + b_hid; comb = [emb | h]
    k_gemm<<<g1, T>>>(p_h1, W_hid, p_xw, N, 128, 128, 128);
    k_selfloop<<<(nv4 + T - 1) / T, T>>>();
    k_edge_agg<<<gEw, T>>>(edge, E);
    k_emb_comb<<<(nv4 + T - 1) / T, T>>>(b_hid, h);

    // GRU gates: zr = comb @ [W_z | W_r]
    k_build_wzr<<<256, 128>>>(W_z, W_r);
    k_gemm<<<g2, T>>>(p_comb, p_wzr, p_zr, N, 256, 256, 256);

    // comb[:,128:] = sigmoid(r_pre + b_r) * h ; cpre = comb @ W_c
    k_rh<<<(nv4 + T - 1) / T, T>>>(b_r, h);
    k_gemm<<<g1, T>>>(p_comb, W_c, p_xw, N, 256, 128, 128);

    // out = (1-u)*h + u*tanh(cpre + b_c)
    k_final<<<(nv4 + T - 1) / T, T>>>(b_z, b_c, h, out);
}

// round 3
// speedup vs baseline: 1.7888x; 1.7888x over previous
#include <cuda_runtime.h>
#include <cuda_bf16.h>
#include <cstdint>

#define NN 50000

// ---------------- scratch (static device globals; no allocation) ----------------
__device__ __align__(16) float g_deg[NN];
__device__ __align__(16) float g_xw[(size_t)NN * 128];      // xw (gather table) / scratch
__device__ __align__(16) float g_agg[(size_t)NN * 128];     // aggregation buffer
__device__ __align__(16) float g_h1[(size_t)NN * 128];      // relu output layer 1
__device__ __align__(16) float g_comb[(size_t)NN * 256];    // [emb | h]
__device__ __align__(16) float g_comb2[(size_t)NN * 256];   // [emb | r*h]
__device__ __align__(16) float g_zr[(size_t)NN * 128];      // z_pre only
__device__ __align__(16) __nv_bfloat16 g_bthi[256 * 256];   // B^T hi (N-major, K contiguous)
__device__ __align__(16) __nv_bfloat16 g_btlo[256 * 256];   // B^T lo

__device__ __forceinline__ float sigmoidf_(float x) { return 1.0f / (1.0f + __expf(-x)); }

__device__ __forceinline__ uint32_t smem_u32(const void* p) {
    uint32_t a;
    asm("{ .reg .u64 t; cvta.to.shared.u64 t, %1; cvt.u32.u64 %0, t; }" : "=r"(a) : "l"(p));
    return a;
}
__device__ __forceinline__ void ldsm4(uint32_t& r0, uint32_t& r1, uint32_t& r2, uint32_t& r3,
                                      uint32_t addr) {
    asm volatile("ldmatrix.sync.aligned.m8n8.x4.shared.b16 {%0,%1,%2,%3}, [%4];"
                 : "=r"(r0), "=r"(r1), "=r"(r2), "=r"(r3) : "r"(addr));
}
__device__ __forceinline__ void mma16816(float* d, const uint32_t* a, uint32_t b0, uint32_t b1) {
    asm volatile(
        "mma.sync.aligned.m16n8k16.row.col.f32.bf16.bf16.f32 "
        "{%0,%1,%2,%3}, {%4,%5,%6,%7}, {%8,%9}, {%0,%1,%2,%3};"
        : "+f"(d[0]), "+f"(d[1]), "+f"(d[2]), "+f"(d[3])
        : "r"(a[0]), "r"(a[1]), "r"(a[2]), "r"(a[3]), "r"(b0), "r"(b1));
}

// ---------------- degree / dinv ----------------
__global__ void k_init_deg() {
    int i = blockIdx.x * blockDim.x + threadIdx.x;
    if (i < NN) g_deg[i] = 1.0f;
}
__global__ void k_deg_atomic(const int* __restrict__ dst, int E) {
    int i = blockIdx.x * blockDim.x + threadIdx.x;
    if (i < E) atomicAdd(&g_deg[dst[i]], 1.0f);
}
__global__ void k_dinv() {
    int i = blockIdx.x * blockDim.x + threadIdx.x;
    if (i < NN) g_deg[i] = rsqrtf(g_deg[i]);
}

// ---------------- weight prep: B[K,N] -> Bt hi/lo [N-major, ldk] ----------------
__global__ void k_prep_b(const float* __restrict__ B, int K, int Nw, int noff, int ldk) {
    int idx = blockIdx.x * blockDim.x + threadIdx.x;
    if (idx >= K * Nw) return;
    int k = idx / Nw, n = idx % Nw;
    float v = B[idx];
    __nv_bfloat16 hi = __float2bfloat16(v);
    __nv_bfloat16 lo = __float2bfloat16(v - __bfloat162float(hi));
    g_bthi[(size_t)(noff + n) * ldk + k] = hi;
    g_btlo[(size_t)(noff + n) * ldk + k] = lo;
}

// ---------------- HMMA split-bf16 GEMM ----------------
// C[M,Nc] = A[M,K] @ B ; CTA tile 128x128, 8 warps (32x64 each), K-chunk 64.
// smem rows padded to 72 bf16 (144B) -> ldmatrix conflict-free.
// MODE 1: C=store + agg = C * dinv[row]^2 (GCN self loop fused)
// MODE 3: cols<128 -> zr (z_pre); cols>=128 -> comb2[.,128+c] = sigmoid(v+br)*h
// MODE 2: out = (1-u)*h + u*tanh(v + bc), u = sigmoid(zr + bz)   (final GRU gate)
#define LDP 72
#define ALO_OFF (128 * LDP * 2)
#define BHI_OFF (2 * 128 * LDP * 2)
#define BLO_OFF (3 * 128 * LDP * 2)
#define GSMEM   (4 * 128 * LDP * 2)

template <int MODE>
__global__ __launch_bounds__(256, 2) void k_gemm_mma(
    const float* __restrict__ A, const __nv_bfloat16* __restrict__ Bh,
    const __nv_bfloat16* __restrict__ Bl, int M, int K,
    float* __restrict__ C, float* __restrict__ aux0, float* __restrict__ aux1,
    const float* __restrict__ p0, const float* __restrict__ p1,
    const float* __restrict__ p2, const float* __restrict__ p3)
{
    extern __shared__ char smem[];
    uint32_t sb = smem_u32(smem);
    int tid = threadIdx.x, lane = tid & 31, wid = tid >> 5;
    int wm = (wid >> 1) * 32, wn = (wid & 1) * 64;
    int bm = blockIdx.x * 128, bn = blockIdx.y * 128;

    float acc[2][8][4];
#pragma unroll
    for (int i = 0; i < 2; i++)
#pragma unroll
        for (int j = 0; j < 8; j++)
#pragma unroll
            for (int t = 0; t < 4; t++) acc[i][j][t] = 0.f;

    // lane-level ldmatrix address components
    uint32_t aRow = lane & 15;                          // row offset within 16
    uint32_t aK   = (lane >> 1) & 8;                    // 0 / 8
    uint32_t bRow = (lane & 7) + ((lane >> 4) & 1) * 8; // n offset within 16
    uint32_t bK   = ((lane >> 3) & 1) * 8;

    for (int k0 = 0; k0 < K; k0 += 64) {
        // cooperative load: A fp32 -> hi/lo bf16, B hi/lo bf16 copy
#pragma unroll
        for (int it = 0; it < 16; it++) {
            int i = tid + it * 256;
            int row = i >> 5;
            int kp = i & 31;                 // uint32 index (2 bf16)
            uint32_t off = row * 144 + kp * 4;
            // A
            int gr = bm + row;
            float2 v = make_float2(0.f, 0.f);
            if (gr < M) v = *(const float2*)&A[(size_t)gr * K + k0 + kp * 2];
            __nv_bfloat16 hx = __float2bfloat16(v.x);
            __nv_bfloat16 hy = __float2bfloat16(v.y);
            __nv_bfloat16 lx = __float2bfloat16(v.x - __bfloat162float(hx));
            __nv_bfloat16 ly = __float2bfloat16(v.y - __bfloat162float(hy));
            *(uint32_t*)(smem + off) =
                ((uint32_t)__bfloat16_as_ushort(hy) << 16) | __bfloat16_as_ushort(hx);
            *(uint32_t*)(smem + ALO_OFF + off) =
                ((uint32_t)__bfloat16_as_ushort(ly) << 16) | __bfloat16_as_ushort(lx);
            // B (always full 128 rows: Nc is a multiple of 128)
            *(uint32_t*)(smem + BHI_OFF + off) =
                *(const uint32_t*)&Bh[(size_t)(bn + row) * K + k0 + kp * 2];
            *(uint32_t*)(smem + BLO_OFF + off) =
                *(const uint32_t*)&Bl[(size_t)(bn + row) * K + k0 + kp * 2];
        }
        __syncthreads();

#pragma unroll
        for (int ks = 0; ks < 4; ks++) {
            uint32_t ah[2][4], al[2][4];
#pragma unroll
            for (int mt = 0; mt < 2; mt++) {
                uint32_t ao = sb + (wm + mt * 16 + aRow) * 144 + (ks * 16 + aK) * 2;
                ldsm4(ah[mt][0], ah[mt][1], ah[mt][2], ah[mt][3], ao);
                ldsm4(al[mt][0], al[mt][1], al[mt][2], al[mt][3], ao + ALO_OFF);
            }
#pragma unroll
            for (int np = 0; np < 4; np++) {
                uint32_t bo = sb + BHI_OFF + (wn + np * 16 + bRow) * 144 + (ks * 16 + bK) * 2;
                uint32_t bh[4], bl[4];
                ldsm4(bh[0], bh[1], bh[2], bh[3], bo);
                ldsm4(bl[0], bl[1], bl[2], bl[3], bo + (BLO_OFF - BHI_OFF));
#pragma unroll
                for (int mt = 0; mt < 2; mt++) {
                    mma16816(acc[mt][np * 2],     ah[mt], bh[0], bh[1]);
                    mma16816(acc[mt][np * 2],     ah[mt], bl[0], bl[1]);
                    mma16816(acc[mt][np * 2],     al[mt], bh[0], bh[1]);
                    mma16816(acc[mt][np * 2 + 1], ah[mt], bh[2], bh[3]);
                    mma16816(acc[mt][np * 2 + 1], ah[mt], bl[2], bl[3]);
                    mma16816(acc[mt][np * 2 + 1], al[mt], bh[2], bh[3]);
                }
            }
        }
        __syncthreads();
    }

    // ---------------- epilogue ----------------
#pragma unroll
    for (int mt = 0; mt < 2; mt++)
#pragma unroll
        for (int nt = 0; nt < 8; nt++) {
            int colg = bn + wn + nt * 8 + ((lane & 3) << 1);
            int rbase = bm + wm + mt * 16 + (lane >> 2);
#pragma unroll
            for (int half = 0; half < 2; half++) {
                int row = rbase + half * 8;
                if (row >= M) continue;
                float vx = acc[mt][nt][half * 2];
                float vy = acc[mt][nt][half * 2 + 1];
                if (MODE == 1) {
                    size_t base = (size_t)row * 128 + colg;
                    *(float2*)&C[base] = make_float2(vx, vy);
                    float dv = p0[row];
                    float cc = dv * dv;
                    *(float2*)&aux0[base] = make_float2(vx * cc, vy * cc);
                } else if (MODE == 3) {
                    if (colg < 128) {
                        *(float2*)&aux0[(size_t)row * 128 + colg] = make_float2(vx, vy);
                    } else {
                        int cc = colg - 128;
                        float2 hv = *(const float2*)&p0[(size_t)row * 128 + cc];
                        float2 bb = *(const float2*)&p1[cc];
                        float2 rr = make_float2(sigmoidf_(vx + bb.x) * hv.x,
                                                sigmoidf_(vy + bb.y) * hv.y);
                        *(float2*)&aux1[(size_t)row * 256 + 128 + cc] = rr;
                    }
                } else {  // MODE 2: final GRU gate
                    size_t base = (size_t)row * 128 + colg;
                    float2 zp = *(const float2*)&p0[base];   // z_pre
                    float2 hv = *(const float2*)&p1[base];   // hidden
                    float2 vbz = *(const float2*)&p2[colg];
                    float2 vbc = *(const float2*)&p3[colg];
                    float u0 = sigmoidf_(zp.x + vbz.x);
                    float u1 = sigmoidf_(zp.y + vbz.y);
                    float c0 = tanhf(vx + vbc.x);
                    float c1 = tanhf(vy + vbc.y);
                    *(float2*)&C[base] = make_float2((1.f - u0) * hv.x + u0 * c0,
                                                     (1.f - u1) * hv.y + u1 * c1);
                }
            }
        }
}

// ---------------- aggregation ----------------
__global__ void k_edge_agg(const int* __restrict__ edge, int E) {
    int t = blockIdx.x * blockDim.x + threadIdx.x;
    int e = t >> 5;
    int lane = t & 31;
    if (e >= E) return;
    int s = edge[e];
    int d = edge[E + e];
    float c = g_deg[s] * g_deg[d];
    float4 v = ((const float4*)g_xw)[s * 32 + lane];
    v.x *= c; v.y *= c; v.z *= c; v.w *= c;
    float* p = &g_agg[(size_t)d * 128 + lane * 4];
    asm volatile("red.global.add.v4.f32 [%0], {%1, %2, %3, %4};"
                 :: "l"(p), "f"(v.x), "f"(v.y), "f"(v.z), "f"(v.w) : "memory");
}

__global__ void k_relu_bias(const float* __restrict__ b) {
    int i = blockIdx.x * blockDim.x + threadIdx.x;
    if (i >= NN * 32) return;
    int c4 = (i & 31) << 2;
    float4 v = ((const float4*)g_agg)[i];
    float4 bb = *(const float4*)&b[c4];
    v.x = fmaxf(v.x + bb.x, 0.f); v.y = fmaxf(v.y + bb.y, 0.f);
    v.z = fmaxf(v.z + bb.z, 0.f); v.w = fmaxf(v.w + bb.w, 0.f);
    ((float4*)g_h1)[i] = v;
}

// emb = agg + b_hid; comb = [emb | h]; comb2 first half = emb
__global__ void k_emb_comb(const float* __restrict__ b, const float* __restrict__ h) {
    int i = blockIdx.x * blockDim.x + threadIdx.x;
    if (i >= NN * 32) return;
    int node = i >> 5;
    int c4 = i & 31;
    float4 v = ((const float4*)g_agg)[i];
    float4 bb = *(const float4*)&b[c4 << 2];
    v.x += bb.x; v.y += bb.y; v.z += bb.z; v.w += bb.w;
    ((float4*)g_comb)[node * 64 + c4] = v;
    ((float4*)g_comb)[node * 64 + 32 + c4] = ((const float4*)h)[i];
    ((float4*)g_comb2)[node * 64 + c4] = v;
}

// ---------------- launcher ----------------
extern "C" void kernel_launch(void* const* d_in, const int* in_sizes, int n_in,
                              void* d_out, int out_size) {
    const float* x     = (const float*)d_in[0];
    const float* h     = (const float*)d_in[1];
    const int*   edge  = (const int*)d_in[2];
    const float* W_in  = (const float*)d_in[3];
    const float* b_in  = (const float*)d_in[4];
    const float* W_hid = (const float*)d_in[5];
    const float* b_hid = (const float*)d_in[6];
    const float* W_z   = (const float*)d_in[7];
    const float* b_z   = (const float*)d_in[8];
    const float* W_r   = (const float*)d_in[9];
    const float* b_r   = (const float*)d_in[10];
    const float* W_c   = (const float*)d_in[11];
    const float* b_c   = (const float*)d_in[12];
    float* out = (float*)d_out;

    const int N = in_sizes[0] / 128;   // 50000
    const int E = in_sizes[2] / 2;     // 600000

    float *p_xw, *p_agg, *p_h1, *p_comb, *p_comb2, *p_zr, *p_deg;
    __nv_bfloat16 *p_bh, *p_bl;
    cudaGetSymbolAddress((void**)&p_xw,    g_xw);
    cudaGetSymbolAddress((void**)&p_agg,   g_agg);
    cudaGetSymbolAddress((void**)&p_h1,    g_h1);
    cudaGetSymbolAddress((void**)&p_comb,  g_comb);
    cudaGetSymbolAddress((void**)&p_comb2, g_comb2);
    cudaGetSymbolAddress((void**)&p_zr,    g_zr);
    cudaGetSymbolAddress((void**)&p_deg,   g_deg);
    cudaGetSymbolAddress((void**)&p_bh,    g_bthi);
    cudaGetSymbolAddress((void**)&p_bl,    g_btlo);

    cudaFuncSetAttribute(k_gemm_mma<1>, cudaFuncAttributeMaxDynamicSharedMemorySize, GSMEM);
    cudaFuncSetAttribute(k_gemm_mma<2>, cudaFuncAttributeMaxDynamicSharedMemorySize, GSMEM);
    cudaFuncSetAttribute(k_gemm_mma<3>, cudaFuncAttributeMaxDynamicSharedMemorySize, GSMEM);

    const int T = 256;
    const int nv4 = NN * 32;
    const int gEw = (E * 32 + T - 1) / T;
    const int mtiles = (N + 127) / 128;   // 391
    dim3 g1(mtiles, 1), g2(mtiles, 2);

    // degree -> dinv
    k_init_deg<<<(NN + T - 1) / T, T>>>();
    k_deg_atomic<<<(E + T - 1) / T, T>>>(edge + E, E);
    k_dinv<<<(NN + T - 1) / T, T>>>();

    // layer 1: xw = x@W_in (+fused selfloop agg); edges; h1 = relu(agg + b_in)
    k_prep_b<<<(128 * 128 + T - 1) / T, T>>>(W_in, 128, 128, 0, 128);
    k_gemm_mma<1><<<g1, T, GSMEM>>>(x, p_bh, p_bl, N, 128, p_xw, p_agg, nullptr,
                                    p_deg, nullptr, nullptr, nullptr);
    k_edge_agg<<<gEw, T>>>(edge, E);
    k_relu_bias<<<(nv4 + T - 1) / T, T>>>(b_in);

    // layer 2: xw = h1@W_hid (+selfloop); edges; emb/comb builds
    k_prep_b<<<(128 * 128 + T - 1) / T, T>>>(W_hid, 128, 128, 0, 128);
    k_gemm_mma<1><<<g1, T, GSMEM>>>(p_h1, p_bh, p_bl, N, 128, p_xw, p_agg, nullptr,
                                    p_deg, nullptr, nullptr, nullptr);
    k_edge_agg<<<gEw, T>>>(edge, E);
    k_emb_comb<<<(nv4 + T - 1) / T, T>>>(b_hid, h);

    // gates: [z_pre | r] = comb @ [W_z|W_r]; r-half fused -> comb2[:,128:]
    k_prep_b<<<(256 * 128 + T - 1) / T, T>>>(W_z, 256, 128, 0,   256);
    k_prep_b<<<(256 * 128 + T - 1) / T, T>>>(W_r, 256, 128, 128, 256);
    k_gemm_mma<3><<<g2, T, GSMEM>>>(p_comb, p_bh, p_bl, N, 256, nullptr, p_zr, p_comb2,
                                    h, b_r, nullptr, nullptr);

    // candidate + final gate fused: out = (1-u)*h + u*tanh(comb2@W_c + b_c)
    k_prep_b<<<(256 * 128 + T - 1) / T, T>>>(W_c, 256, 128, 0, 256);
    k_gemm_mma<2><<<g1, T, GSMEM>>>(p_comb2, p_bh, p_bl, N, 256, out, nullptr, nullptr,
                                    p_zr, h, b_z, b_c);
}

// round 4
// speedup vs baseline: 2.3066x; 1.2895x over previous
#include <cuda_runtime.h>
#include <cuda_bf16.h>
#include <cstdint>

#define NN 50000
#define NB ((NN + 255) / 256)   // 196 scan blocks

// ---------------- scratch (static device globals; no allocation) ----------------
__device__ __align__(16) float g_deg[NN];                     // dinv
__device__ __align__(16) int   g_cnt[NN];
__device__ __align__(16) int   g_rowptr[NN + 1];
__device__ __align__(16) int   g_cursor[NN];
__device__ __align__(16) int   g_bsum[256];
__device__ __align__(16) int   g_csrsrc[600000];
__device__ __align__(16) float g_xw[(size_t)NN * 128];        // xw gather table
__device__ __align__(16) float g_h1[(size_t)NN * 128];
__device__ __align__(16) float g_comb[(size_t)NN * 256];      // [emb | h]
__device__ __align__(16) float g_comb2[(size_t)NN * 256];     // [emb | r*h]
__device__ __align__(16) float g_zr[(size_t)NN * 128];        // z_pre
__device__ __align__(16) __nv_bfloat16 g_bthi[131072];        // all weights, hi split
__device__ __align__(16) __nv_bfloat16 g_btlo[131072];        // all weights, lo split

__device__ __forceinline__ float sigmoidf_(float x) { return 1.0f / (1.0f + __expf(-x)); }

__device__ __forceinline__ uint32_t smem_u32(const void* p) {
    uint32_t a;
    asm("{ .reg .u64 t; cvta.to.shared.u64 t, %1; cvt.u32.u64 %0, t; }" : "=r"(a) : "l"(p));
    return a;
}
__device__ __forceinline__ void ldsm4(uint32_t& r0, uint32_t& r1, uint32_t& r2, uint32_t& r3,
                                      uint32_t addr) {
    asm volatile("ldmatrix.sync.aligned.m8n8.x4.shared.b16 {%0,%1,%2,%3}, [%4];"
                 : "=r"(r0), "=r"(r1), "=r"(r2), "=r"(r3) : "r"(addr));
}
__device__ __forceinline__ void mma16816(float* d, const uint32_t* a, uint32_t b0, uint32_t b1) {
    asm volatile(
        "mma.sync.aligned.m16n8k16.row.col.f32.bf16.bf16.f32 "
        "{%0,%1,%2,%3}, {%4,%5,%6,%7}, {%8,%9}, {%0,%1,%2,%3};"
        : "+f"(d[0]), "+f"(d[1]), "+f"(d[2]), "+f"(d[3])
        : "r"(a[0]), "r"(a[1]), "r"(a[2]), "r"(a[3]), "r"(b0), "r"(b1));
}

// ---------------- CSR build ----------------
__global__ void k_zero_cnt() {
    int i = blockIdx.x * blockDim.x + threadIdx.x;
    if (i < NN) g_cnt[i] = 0;
}
__global__ void k_hist(const int* __restrict__ dst, int E) {
    int i = blockIdx.x * blockDim.x + threadIdx.x;
    if (i < E) atomicAdd(&g_cnt[dst[i]], 1);
}
__global__ void k_scan_block() {
    __shared__ int sh[256];
    int tid = threadIdx.x;
    int i = blockIdx.x * 256 + tid;
    int v = (i < NN) ? g_cnt[i] : 0;
    sh[tid] = v;
    __syncthreads();
#pragma unroll
    for (int off = 1; off < 256; off <<= 1) {
        int t = (tid >= off) ? sh[tid - off] : 0;
        __syncthreads();
        sh[tid] += t;
        __syncthreads();
    }
    if (i < NN) g_rowptr[i] = sh[tid] - v;         // exclusive, block-local
    if (tid == 255) g_bsum[blockIdx.x] = sh[255];
}
__global__ void k_scan_top() {
    __shared__ int sh[256];
    int tid = threadIdx.x;
    int v = (tid < NB) ? g_bsum[tid] : 0;
    sh[tid] = v;
    __syncthreads();
#pragma unroll
    for (int off = 1; off < 256; off <<= 1) {
        int t = (tid >= off) ? sh[tid - off] : 0;
        __syncthreads();
        sh[tid] += t;
        __syncthreads();
    }
    if (tid < NB) g_bsum[tid] = sh[tid] - v;       // exclusive
}
__global__ void k_scan_fin(int E) {
    int i = blockIdx.x * blockDim.x + threadIdx.x;
    if (i >= NN) return;
    int r = g_rowptr[i] + g_bsum[i >> 8];
    g_rowptr[i] = r;
    g_cursor[i] = r;
    g_deg[i] = rsqrtf((float)(g_cnt[i] + 1));      // dinv (self loop included)
    if (i == NN - 1) g_rowptr[NN] = E;
}
__global__ void k_scatter(const int* __restrict__ edge, int E) {
    int i = blockIdx.x * blockDim.x + threadIdx.x;
    if (i >= E) return;
    int d = edge[E + i];
    int pos = atomicAdd(&g_cursor[d], 1);
    g_csrsrc[pos] = edge[i];
}

// ---------------- weight prep: all 5 weight matrices -> hi/lo N-major ----------------
// layout (bf16 elems): [0) W_in 128x128 ldk128 | [16384) W_hid | [32768) Wz|Wr 256 rows ldk256 | [98304) Wc 128 rows ldk256
__global__ void k_prep_all(const float* __restrict__ Win, const float* __restrict__ Whid,
                           const float* __restrict__ Wz, const float* __restrict__ Wr,
                           const float* __restrict__ Wc) {
    int idx = blockIdx.x * blockDim.x + threadIdx.x;
    if (idx >= 131072) return;
    float v; int dst;
    if (idx < 16384) {
        int k = idx >> 7, n = idx & 127;
        v = Win[idx]; dst = n * 128 + k;
    } else if (idx < 32768) {
        int i2 = idx - 16384; int k = i2 >> 7, n = i2 & 127;
        v = Whid[i2]; dst = 16384 + n * 128 + k;
    } else if (idx < 65536) {
        int i2 = idx - 32768; int k = i2 >> 7, n = i2 & 127;
        v = Wz[i2]; dst = 32768 + n * 256 + k;
    } else if (idx < 98304) {
        int i2 = idx - 65536; int k = i2 >> 7, n = i2 & 127;
        v = Wr[i2]; dst = 32768 + (128 + n) * 256 + k;
    } else {
        int i2 = idx - 98304; int k = i2 >> 7, n = i2 & 127;
        v = Wc[i2]; dst = 98304 + n * 256 + k;
    }
    __nv_bfloat16 hi = __float2bfloat16(v);
    __nv_bfloat16 lo = __float2bfloat16(v - __bfloat162float(hi));
    g_bthi[dst] = hi;
    g_btlo[dst] = lo;
}

// ---------------- HMMA split-bf16 GEMM ----------------
// MODE 0: plain store C. MODE 3: zr / r-gate split. MODE 2: final GRU gate.
#define ALO_OFF (128 * 144)
#define BHI_OFF (2 * 128 * 144)
#define BLO_OFF (3 * 128 * 144)
#define GSMEM   (4 * 128 * 144)

template <int MODE>
__global__ __launch_bounds__(256, 2) void k_gemm_mma(
    const float* __restrict__ A, const __nv_bfloat16* __restrict__ Bh,
    const __nv_bfloat16* __restrict__ Bl, int M, int K,
    float* __restrict__ C, float* __restrict__ aux0, float* __restrict__ aux1,
    const float* __restrict__ p0, const float* __restrict__ p1,
    const float* __restrict__ p2, const float* __restrict__ p3)
{
    extern __shared__ char smem[];
    uint32_t sb = smem_u32(smem);
    int tid = threadIdx.x, lane = tid & 31, wid = tid >> 5;
    int wm = (wid >> 1) * 32, wn = (wid & 1) * 64;
    int bm = blockIdx.x * 128, bn = blockIdx.y * 128;

    float acc[2][8][4];
#pragma unroll
    for (int i = 0; i < 2; i++)
#pragma unroll
        for (int j = 0; j < 8; j++)
#pragma unroll
            for (int t = 0; t < 4; t++) acc[i][j][t] = 0.f;

    uint32_t aRow = lane & 15;
    uint32_t aK   = (lane >> 1) & 8;
    uint32_t bRow = (lane & 7) + ((lane >> 4) & 1) * 8;
    uint32_t bK   = ((lane >> 3) & 1) * 8;

    for (int k0 = 0; k0 < K; k0 += 64) {
#pragma unroll
        for (int it = 0; it < 16; it++) {
            int i = tid + it * 256;
            int row = i >> 5;
            int kp = i & 31;
            uint32_t off = row * 144 + kp * 4;
            int gr = bm + row;
            float2 v = make_float2(0.f, 0.f);
            if (gr < M) v = *(const float2*)&A[(size_t)gr * K + k0 + kp * 2];
            __nv_bfloat16 hx = __float2bfloat16(v.x);
            __nv_bfloat16 hy = __float2bfloat16(v.y);
            __nv_bfloat16 lx = __float2bfloat16(v.x - __bfloat162float(hx));
            __nv_bfloat16 ly = __float2bfloat16(v.y - __bfloat162float(hy));
            *(uint32_t*)(smem + off) =
                ((uint32_t)__bfloat16_as_ushort(hy) << 16) | __bfloat16_as_ushort(hx);
            *(uint32_t*)(smem + ALO_OFF + off) =
                ((uint32_t)__bfloat16_as_ushort(ly) << 16) | __bfloat16_as_ushort(lx);
            *(uint32_t*)(smem + BHI_OFF + off) =
                *(const uint32_t*)&Bh[(size_t)(bn + row) * K + k0 + kp * 2];
            *(uint32_t*)(smem + BLO_OFF + off) =
                *(const uint32_t*)&Bl[(size_t)(bn + row) * K + k0 + kp * 2];
        }
        __syncthreads();

#pragma unroll
        for (int ks = 0; ks < 4; ks++) {
            uint32_t ah[2][4], al[2][4];
#pragma unroll
            for (int mt = 0; mt < 2; mt++) {
                uint32_t ao = sb + (wm + mt * 16 + aRow) * 144 + (ks * 16 + aK) * 2;
                ldsm4(ah[mt][0], ah[mt][1], ah[mt][2], ah[mt][3], ao);
                ldsm4(al[mt][0], al[mt][1], al[mt][2], al[mt][3], ao + ALO_OFF);
            }
#pragma unroll
            for (int np = 0; np < 4; np++) {
                uint32_t bo = sb + BHI_OFF + (wn + np * 16 + bRow) * 144 + (ks * 16 + bK) * 2;
                uint32_t bh[4], bl[4];
                ldsm4(bh[0], bh[1], bh[2], bh[3], bo);
                ldsm4(bl[0], bl[1], bl[2], bl[3], bo + (BLO_OFF - BHI_OFF));
#pragma unroll
                for (int mt = 0; mt < 2; mt++) {
                    mma16816(acc[mt][np * 2],     ah[mt], bh[0], bh[1]);
                    mma16816(acc[mt][np * 2],     ah[mt], bl[0], bl[1]);
                    mma16816(acc[mt][np * 2],     al[mt], bh[0], bh[1]);
                    mma16816(acc[mt][np * 2 + 1], ah[mt], bh[2], bh[3]);
                    mma16816(acc[mt][np * 2 + 1], ah[mt], bl[2], bl[3]);
                    mma16816(acc[mt][np * 2 + 1], al[mt], bh[2], bh[3]);
                }
            }
        }
        __syncthreads();
    }

#pragma unroll
    for (int mt = 0; mt < 2; mt++)
#pragma unroll
        for (int nt = 0; nt < 8; nt++) {
            int colg = bn + wn + nt * 8 + ((lane & 3) << 1);
            int rbase = bm + wm + mt * 16 + (lane >> 2);
#pragma unroll
            for (int half = 0; half < 2; half++) {
                int row = rbase + half * 8;
                if (row >= M) continue;
                float vx = acc[mt][nt][half * 2];
                float vy = acc[mt][nt][half * 2 + 1];
                if (MODE == 0) {
                    *(float2*)&C[(size_t)row * 128 + colg] = make_float2(vx, vy);
                } else if (MODE == 3) {
                    if (colg < 128) {
                        *(float2*)&aux0[(size_t)row * 128 + colg] = make_float2(vx, vy);
                    } else {
                        int cc = colg - 128;
                        float2 hv = *(const float2*)&p0[(size_t)row * 128 + cc];
                        float2 bb = *(const float2*)&p1[cc];
                        float2 rr = make_float2(sigmoidf_(vx + bb.x) * hv.x,
                                                sigmoidf_(vy + bb.y) * hv.y);
                        *(float2*)&aux1[(size_t)row * 256 + 128 + cc] = rr;
                    }
                } else {  // MODE 2
                    size_t base = (size_t)row * 128 + colg;
                    float2 zp = *(const float2*)&p0[base];
                    float2 hv = *(const float2*)&p1[base];
                    float2 vbz = *(const float2*)&p2[colg];
                    float2 vbc = *(const float2*)&p3[colg];
                    float u0 = sigmoidf_(zp.x + vbz.x);
                    float u1 = sigmoidf_(zp.y + vbz.y);
                    float c0 = tanhf(vx + vbc.x);
                    float c1 = tanhf(vy + vbc.y);
                    *(float2*)&C[base] = make_float2((1.f - u0) * hv.x + u0 * c0,
                                                     (1.f - u1) * hv.y + u1 * c1);
                }
            }
        }
}

// ---------------- CSR aggregation: warp per dst node, no atomics ----------------
// LAYER 1: h1 = relu(agg + b_in).  LAYER 2: emb = agg + b_hid; comb=[emb|h]; comb2[:, :128]=emb
template <int LAYER>
__global__ __launch_bounds__(256) void k_agg_csr(const float* __restrict__ b,
                                                 const float* __restrict__ h) {
    int w = blockIdx.x * 8 + (threadIdx.x >> 5);
    if (w >= NN) return;
    int lane = threadIdx.x & 31;
    const float4* xw4 = (const float4*)g_xw;

    float dd = g_deg[w];
    float4 acc = xw4[(size_t)w * 32 + lane];
    float cself = dd * dd;
    acc.x *= cself; acc.y *= cself; acc.z *= cself; acc.w *= cself;

    int start = g_rowptr[w], end = g_rowptr[w + 1];
    for (int base = start; base < end; base += 32) {
        int e = base + lane;
        int sv = 0; float dv = 0.f;
        if (e < end) { sv = g_csrsrc[e]; dv = g_deg[sv]; }
        int cnt = end - base; if (cnt > 32) cnt = 32;
        for (int j = 0; j < cnt; j++) {
            int s = __shfl_sync(0xffffffffu, sv, j);
            float c = __shfl_sync(0xffffffffu, dv, j) * dd;
            float4 v = xw4[(size_t)s * 32 + lane];
            acc.x += v.x * c; acc.y += v.y * c; acc.z += v.z * c; acc.w += v.w * c;
        }
    }

    float4 bb = *(const float4*)&b[lane * 4];
    acc.x += bb.x; acc.y += bb.y; acc.z += bb.z; acc.w += bb.w;
    if (LAYER == 1) {
        acc.x = fmaxf(acc.x, 0.f); acc.y = fmaxf(acc.y, 0.f);
        acc.z = fmaxf(acc.z, 0.f); acc.w = fmaxf(acc.w, 0.f);
        ((float4*)g_h1)[(size_t)w * 32 + lane] = acc;
    } else {
        float4 hv = ((const float4*)h)[(size_t)w * 32 + lane];
        ((float4*)&g_comb[(size_t)w * 256])[lane] = acc;
        ((float4*)&g_comb[(size_t)w * 256 + 128])[lane] = hv;
        ((float4*)&g_comb2[(size_t)w * 256])[lane] = acc;
    }
}

// ---------------- launcher ----------------
extern "C" void kernel_launch(void* const* d_in, const int* in_sizes, int n_in,
                              void* d_out, int out_size) {
    const float* x     = (const float*)d_in[0];
    const float* h     = (const float*)d_in[1];
    const int*   edge  = (const int*)d_in[2];
    const float* W_in  = (const float*)d_in[3];
    const float* b_in  = (const float*)d_in[4];
    const float* W_hid = (const float*)d_in[5];
    const float* b_hid = (const float*)d_in[6];
    const float* W_z   = (const float*)d_in[7];
    const float* b_z   = (const float*)d_in[8];
    const float* W_r   = (const float*)d_in[9];
    const float* b_r   = (const float*)d_in[10];
    const float* W_c   = (const float*)d_in[11];
    const float* b_c   = (const float*)d_in[12];
    float* out = (float*)d_out;

    const int N = in_sizes[0] / 128;   // 50000
    const int E = in_sizes[2] / 2;     // 600000

    float *p_xw, *p_h1, *p_comb, *p_comb2, *p_zr;
    __nv_bfloat16 *p_bh, *p_bl;
    cudaGetSymbolAddress((void**)&p_xw,    g_xw);
    cudaGetSymbolAddress((void**)&p_h1,    g_h1);
    cudaGetSymbolAddress((void**)&p_comb,  g_comb);
    cudaGetSymbolAddress((void**)&p_comb2, g_comb2);
    cudaGetSymbolAddress((void**)&p_zr,    g_zr);
    cudaGetSymbolAddress((void**)&p_bh,    g_bthi);
    cudaGetSymbolAddress((void**)&p_bl,    g_btlo);

    cudaFuncSetAttribute(k_gemm_mma<0>, cudaFuncAttributeMaxDynamicSharedMemorySize, GSMEM);
    cudaFuncSetAttribute(k_gemm_mma<2>, cudaFuncAttributeMaxDynamicSharedMemorySize, GSMEM);
    cudaFuncSetAttribute(k_gemm_mma<3>, cudaFuncAttributeMaxDynamicSharedMemorySize, GSMEM);

    const int T = 256;
    const int mtiles = (N + 127) / 128;   // 391
    dim3 g1(mtiles, 1), g2(mtiles, 2);
    const int aggB = (NN + 7) / 8;        // 8 warps per block

    // CSR build (graph shared by both layers) + dinv
    k_zero_cnt<<<(NN + T - 1) / T, T>>>();
    k_hist<<<(E + T - 1) / T, T>>>(edge + E, E);
    k_scan_block<<<NB, 256>>>();
    k_scan_top<<<1, 256>>>();
    k_scan_fin<<<(NN + T - 1) / T, T>>>(E);
    k_scatter<<<(E + T - 1) / T, T>>>(edge, E);

    // all weight splits in one launch
    k_prep_all<<<512, 256>>>(W_in, W_hid, W_z, W_r, W_c);

    // layer 1
    k_gemm_mma<0><<<g1, T, GSMEM>>>(x, p_bh, p_bl, N, 128, p_xw, nullptr, nullptr,
                                    nullptr, nullptr, nullptr, nullptr);
    k_agg_csr<1><<<aggB, T>>>(b_in, nullptr);

    // layer 2
    k_gemm_mma<0><<<g1, T, GSMEM>>>(p_h1, p_bh + 16384, p_bl + 16384, N, 128, p_xw,
                                    nullptr, nullptr, nullptr, nullptr, nullptr, nullptr);
    k_agg_csr<2><<<aggB, T>>>(b_hid, h);

    // gates: [z_pre | r] = comb @ [Wz|Wr]; r-half fused into comb2 upper
    k_gemm_mma<3><<<g2, T, GSMEM>>>(p_comb, p_bh + 32768, p_bl + 32768, N, 256,
                                    nullptr, p_zr, p_comb2, h, b_r, nullptr, nullptr);

    // out = (1-u)*h + u*tanh(comb2@Wc + b_c)
    k_gemm_mma<2><<<g1, T, GSMEM>>>(p_comb2, p_bh + 98304, p_bl + 98304, N, 256,
                                    out, nullptr, nullptr, p_zr, h, b_z, b_c);
}

// round 5
// speedup vs baseline: 2.3851x; 1.0340x over previous
#include <cuda_runtime.h>
#include <cuda_bf16.h>
#include <cstdint>

#define NN 50000
#define NB ((NN + 255) / 256)

// ---------------- scratch ----------------
__device__ __align__(16) float g_deg[NN];
__device__ __align__(16) int   g_cnt[NN];
__device__ __align__(16) int   g_rowptr[NN + 1];
__device__ __align__(16) int   g_cursor[NN];
__device__ __align__(16) int   g_bsum[256];
__device__ __align__(16) int   g_csrsrc[600000];
__device__ __align__(16) float g_xw[(size_t)NN * 128];        // GEMM out / gather table (fp32)
__device__ __align__(16) float g_zr[(size_t)NN * 128];        // z_pre
__device__ __align__(16) __nv_bfloat16 g_xh[(size_t)NN * 128],  g_xl[(size_t)NN * 128];
__device__ __align__(16) __nv_bfloat16 g_h1h[(size_t)NN * 128], g_h1l[(size_t)NN * 128];
__device__ __align__(16) __nv_bfloat16 g_cbh[(size_t)NN * 256], g_cbl[(size_t)NN * 256];
__device__ __align__(16) __nv_bfloat16 g_c2h[(size_t)NN * 256], g_c2l[(size_t)NN * 256];
__device__ __align__(16) __nv_bfloat16 g_bthi[131072], g_btlo[131072];

__device__ __forceinline__ float sigmoidf_(float x) { return 1.0f / (1.0f + __expf(-x)); }

__device__ __forceinline__ uint32_t smem_u32(const void* p) {
    uint32_t a;
    asm("{ .reg .u64 t; cvta.to.shared.u64 t, %1; cvt.u32.u64 %0, t; }" : "=r"(a) : "l"(p));
    return a;
}
__device__ __forceinline__ void ldsm4(uint32_t& r0, uint32_t& r1, uint32_t& r2, uint32_t& r3,
                                      uint32_t addr) {
    asm volatile("ldmatrix.sync.aligned.m8n8.x4.shared.b16 {%0,%1,%2,%3}, [%4];"
                 : "=r"(r0), "=r"(r1), "=r"(r2), "=r"(r3) : "r"(addr));
}
__device__ __forceinline__ void mma16816(float* d, const uint32_t* a, uint32_t b0, uint32_t b1) {
    asm volatile(
        "mma.sync.aligned.m16n8k16.row.col.f32.bf16.bf16.f32 "
        "{%0,%1,%2,%3}, {%4,%5,%6,%7}, {%8,%9}, {%0,%1,%2,%3};"
        : "+f"(d[0]), "+f"(d[1]), "+f"(d[2]), "+f"(d[3])
        : "r"(a[0]), "r"(a[1]), "r"(a[2]), "r"(a[3]), "r"(b0), "r"(b1));
}
// split two fp32 -> packed bf16x2 hi (ret) and lo (out param)
__device__ __forceinline__ uint32_t pk2(float x, float y, uint32_t& lo2) {
    __nv_bfloat16 hx = __float2bfloat16(x), hy = __float2bfloat16(y);
    __nv_bfloat16 lx = __float2bfloat16(x - __bfloat162float(hx));
    __nv_bfloat16 ly = __float2bfloat16(y - __bfloat162float(hy));
    lo2 = ((uint32_t)__bfloat16_as_ushort(ly) << 16) | __bfloat16_as_ushort(lx);
    return ((uint32_t)__bfloat16_as_ushort(hy) << 16) | __bfloat16_as_ushort(hx);
}

// ---------------- CSR build ----------------
__global__ void k_zero_cnt() {
    int i = blockIdx.x * blockDim.x + threadIdx.x;
    if (i < NN) g_cnt[i] = 0;
}
__global__ void k_hist(const int* __restrict__ dst, int E) {
    int i = blockIdx.x * blockDim.x + threadIdx.x;
    if (i < E) atomicAdd(&g_cnt[dst[i]], 1);
}
__global__ void k_scan_block() {
    __shared__ int sh[256];
    int tid = threadIdx.x;
    int i = blockIdx.x * 256 + tid;
    int v = (i < NN) ? g_cnt[i] : 0;
    sh[tid] = v;
    __syncthreads();
#pragma unroll
    for (int off = 1; off < 256; off <<= 1) {
        int t = (tid >= off) ? sh[tid - off] : 0;
        __syncthreads();
        sh[tid] += t;
        __syncthreads();
    }
    if (i < NN) g_rowptr[i] = sh[tid] - v;
    if (tid == 255) g_bsum[blockIdx.x] = sh[255];
}
__global__ void k_scan_top() {
    __shared__ int sh[256];
    int tid = threadIdx.x;
    int v = (tid < NB) ? g_bsum[tid] : 0;
    sh[tid] = v;
    __syncthreads();
#pragma unroll
    for (int off = 1; off < 256; off <<= 1) {
        int t = (tid >= off) ? sh[tid - off] : 0;
        __syncthreads();
        sh[tid] += t;
        __syncthreads();
    }
    if (tid < NB) g_bsum[tid] = sh[tid] - v;
}
__global__ void k_scan_fin(int E) {
    int i = blockIdx.x * blockDim.x + threadIdx.x;
    if (i >= NN) return;
    int r = g_rowptr[i] + g_bsum[i >> 8];
    g_rowptr[i] = r;
    g_cursor[i] = r;
    g_deg[i] = rsqrtf((float)(g_cnt[i] + 1));
    if (i == NN - 1) g_rowptr[NN] = E;
}
__global__ void k_scatter(const int* __restrict__ edge, int E) {
    int i = blockIdx.x * blockDim.x + threadIdx.x;
    if (i >= E) return;
    int d = edge[E + i];
    int pos = atomicAdd(&g_cursor[d], 1);
    g_csrsrc[pos] = edge[i];
}

// ---------------- weight prep ----------------
__global__ void k_prep_all(const float* __restrict__ Win, const float* __restrict__ Whid,
                           const float* __restrict__ Wz, const float* __restrict__ Wr,
                           const float* __restrict__ Wc) {
    int idx = blockIdx.x * blockDim.x + threadIdx.x;
    if (idx >= 131072) return;
    float v; int dst;
    if (idx < 16384) {
        int k = idx >> 7, n = idx & 127;
        v = Win[idx]; dst = n * 128 + k;
    } else if (idx < 32768) {
        int i2 = idx - 16384; int k = i2 >> 7, n = i2 & 127;
        v = Whid[i2]; dst = 16384 + n * 128 + k;
    } else if (idx < 65536) {
        int i2 = idx - 32768; int k = i2 >> 7, n = i2 & 127;
        v = Wz[i2]; dst = 32768 + n * 256 + k;
    } else if (idx < 98304) {
        int i2 = idx - 65536; int k = i2 >> 7, n = i2 & 127;
        v = Wr[i2]; dst = 32768 + (128 + n) * 256 + k;
    } else {
        int i2 = idx - 98304; int k = i2 >> 7, n = i2 & 127;
        v = Wc[i2]; dst = 98304 + n * 256 + k;
    }
    __nv_bfloat16 hi = __float2bfloat16(v);
    __nv_bfloat16 lo = __float2bfloat16(v - __bfloat162float(hi));
    g_bthi[dst] = hi;
    g_btlo[dst] = lo;
}

// ---------------- split x -> bf16 hi/lo planes ----------------
__global__ void k_split_x(const float* __restrict__ x) {
    int i = blockIdx.x * blockDim.x + threadIdx.x;
    if (i >= NN * 32) return;
    float4 v = ((const float4*)x)[i];
    uint32_t l0, l1;
    uint32_t h0 = pk2(v.x, v.y, l0);
    uint32_t h1 = pk2(v.z, v.w, l1);
    ((uint2*)g_xh)[i] = make_uint2(h0, h1);
    ((uint2*)g_xl)[i] = make_uint2(l0, l1);
}

// ---------------- HMMA GEMM: pre-split A/B, cp.async double-buffered ----------------
// K-chunk 32, rows padded to 80B. Planes: Ahi, Alo, Bhi, Blo.
#define PLS 10240            // 128 * 80
#define BUFS (4 * PLS)       // 40960
#define GSMEM (2 * BUFS)     // 81920

template <int MODE>
__global__ __launch_bounds__(256, 2) void k_gemm3(
    const __nv_bfloat16* __restrict__ Ah, const __nv_bfloat16* __restrict__ Al,
    const __nv_bfloat16* __restrict__ Bh, const __nv_bfloat16* __restrict__ Bl,
    int M, int K,
    float* __restrict__ C, float* __restrict__ zr,
    __nv_bfloat16* __restrict__ c2h, __nv_bfloat16* __restrict__ c2l,
    const float* __restrict__ p0, const float* __restrict__ p1,
    const float* __restrict__ p2, const float* __restrict__ p3)
{
    extern __shared__ char smem[];
    uint32_t sb = smem_u32(smem);
    int tid = threadIdx.x, lane = tid & 31, wid = tid >> 5;
    int wm = (wid >> 1) * 32, wn = (wid & 1) * 64;
    int bm = blockIdx.x * 128, bn = blockIdx.y * 128;

    float acc[2][8][4];
#pragma unroll
    for (int i = 0; i < 2; i++)
#pragma unroll
        for (int j = 0; j < 8; j++)
#pragma unroll
            for (int t = 0; t < 4; t++) acc[i][j][t] = 0.f;

    uint32_t aRow = lane & 15;
    uint32_t aK   = (lane >> 1) & 8;
    uint32_t bRow = (lane & 7) + ((lane >> 4) & 1) * 8;
    uint32_t bK   = ((lane >> 3) & 1) * 8;

    const __nv_bfloat16* gp[4] = {Ah, Al, Bh, Bl};
    int ldrow = tid >> 2, ldseg = tid & 3;        // 64 rows per 256-thread pass? -> i>>2 covers 0..63
    // each plane: 128 rows x 4 segs = 512 ops; 256 threads -> 2 per thread per plane

    auto load_chunk = [&](int buf, int c) {
        int k0 = c << 5;
#pragma unroll
        for (int pl = 0; pl < 4; pl++) {
            const __nv_bfloat16* g = gp[pl];
#pragma unroll
            for (int it = 0; it < 2; it++) {
                int i = tid + it * 256;
                int row = i >> 2, seg = i & 3;
                uint32_t dst = sb + buf * BUFS + pl * PLS + row * 80 + seg * 16;
                int gr = (pl < 2) ? min(bm + row, M - 1) : (bn + row);
                const __nv_bfloat16* src = g + (size_t)gr * K + k0 + seg * 8;
                asm volatile("cp.async.cg.shared.global [%0], [%1], 16;"
                             :: "r"(dst), "l"(src));
            }
        }
        asm volatile("cp.async.commit_group;" ::: "memory");
    };

    auto compute_chunk = [&](int buf) {
        uint32_t base = sb + buf * BUFS;
#pragma unroll
        for (int ks = 0; ks < 2; ks++) {
            uint32_t ah[2][4], al[2][4];
#pragma unroll
            for (int mt = 0; mt < 2; mt++) {
                uint32_t ao = base + (wm + mt * 16 + aRow) * 80 + (ks * 16 + aK) * 2;
                ldsm4(ah[mt][0], ah[mt][1], ah[mt][2], ah[mt][3], ao);
                ldsm4(al[mt][0], al[mt][1], al[mt][2], al[mt][3], ao + PLS);
            }
#pragma unroll
            for (int np = 0; np < 4; np++) {
                uint32_t bo = base + 2 * PLS + (wn + np * 16 + bRow) * 80 + (ks * 16 + bK) * 2;
                uint32_t bh[4], bl[4];
                ldsm4(bh[0], bh[1], bh[2], bh[3], bo);
                ldsm4(bl[0], bl[1], bl[2], bl[3], bo + PLS);
#pragma unroll
                for (int mt = 0; mt < 2; mt++) {
                    mma16816(acc[mt][np * 2],     ah[mt], bh[0], bh[1]);
                    mma16816(acc[mt][np * 2],     ah[mt], bl[0], bl[1]);
                    mma16816(acc[mt][np * 2],     al[mt], bh[0], bh[1]);
                    mma16816(acc[mt][np * 2 + 1], ah[mt], bh[2], bh[3]);
                    mma16816(acc[mt][np * 2 + 1], ah[mt], bl[2], bl[3]);
                    mma16816(acc[mt][np * 2 + 1], al[mt], bh[2], bh[3]);
                }
            }
        }
    };

    int nc = K >> 5;
    load_chunk(0, 0);
    for (int c = 0; c < nc; c++) {
        if (c + 1 < nc) {
            load_chunk((c + 1) & 1, c + 1);
            asm volatile("cp.async.wait_group 1;" ::: "memory");
        } else {
            asm volatile("cp.async.wait_group 0;" ::: "memory");
        }
        __syncthreads();
        compute_chunk(c & 1);
        __syncthreads();
    }

    // ---------------- epilogue ----------------
#pragma unroll
    for (int mt = 0; mt < 2; mt++)
#pragma unroll
        for (int nt = 0; nt < 8; nt++) {
            int colg = bn + wn + nt * 8 + ((lane & 3) << 1);
            int rbase = bm + wm + mt * 16 + (lane >> 2);
#pragma unroll
            for (int half = 0; half < 2; half++) {
                int row = rbase + half * 8;
                if (row >= M) continue;
                float vx = acc[mt][nt][half * 2];
                float vy = acc[mt][nt][half * 2 + 1];
                if (MODE == 0) {
                    *(float2*)&C[(size_t)row * 128 + colg] = make_float2(vx, vy);
                } else if (MODE == 3) {
                    if (colg < 128) {
                        *(float2*)&zr[(size_t)row * 128 + colg] = make_float2(vx, vy);
                    } else {
                        int cc = colg - 128;
                        float2 hv = *(const float2*)&p0[(size_t)row * 128 + cc];
                        float2 bb = *(const float2*)&p1[cc];
                        float rx = sigmoidf_(vx + bb.x) * hv.x;
                        float ry = sigmoidf_(vy + bb.y) * hv.y;
                        uint32_t lo;
                        uint32_t hi = pk2(rx, ry, lo);
                        size_t idx = ((size_t)row * 256 + 128 + cc) >> 1;
                        ((uint32_t*)c2h)[idx] = hi;
                        ((uint32_t*)c2l)[idx] = lo;
                    }
                } else {  // MODE 2
                    size_t base = (size_t)row * 128 + colg;
                    float2 zp = *(const float2*)&p0[base];
                    float2 hv = *(const float2*)&p1[base];
                    float2 vbz = *(const float2*)&p2[colg];
                    float2 vbc = *(const float2*)&p3[colg];
                    float u0 = sigmoidf_(zp.x + vbz.x);
                    float u1 = sigmoidf_(zp.y + vbz.y);
                    float c0 = tanhf(vx + vbc.x);
                    float c1 = tanhf(vy + vbc.y);
                    *(float2*)&C[base] = make_float2((1.f - u0) * hv.x + u0 * c0,
                                                     (1.f - u1) * hv.y + u1 * c1);
                }
            }
        }
}

// ---------------- CSR aggregation: warp per dst node ----------------
// LAYER 1: h1 = relu(agg + b_in) -> split bf16. LAYER 2: emb -> comb/comb2 splits, h -> comb.
template <int LAYER>
__global__ __launch_bounds__(256) void k_agg_csr(const float* __restrict__ b,
                                                 const float* __restrict__ h) {
    int w = blockIdx.x * 8 + (threadIdx.x >> 5);
    if (w >= NN) return;
    int lane = threadIdx.x & 31;
    const float4* xw4 = (const float4*)g_xw;

    float dd = g_deg[w];
    float4 acc = xw4[(size_t)w * 32 + lane];
    float cself = dd * dd;
    acc.x *= cself; acc.y *= cself; acc.z *= cself; acc.w *= cself;

    int start = g_rowptr[w], end = g_rowptr[w + 1];
    for (int base = start; base < end; base += 32) {
        int e = base + lane;
        int sv = 0; float dv = 0.f;
        if (e < end) { sv = g_csrsrc[e]; dv = g_deg[sv]; }
        int cnt = end - base; if (cnt > 32) cnt = 32;
        for (int j = 0; j < cnt; j++) {
            int s = __shfl_sync(0xffffffffu, sv, j);
            float c = __shfl_sync(0xffffffffu, dv, j) * dd;
            float4 v = xw4[(size_t)s * 32 + lane];
            acc.x += v.x * c; acc.y += v.y * c; acc.z += v.z * c; acc.w += v.w * c;
        }
    }

    float4 bb = *(const float4*)&b[lane * 4];
    acc.x += bb.x; acc.y += bb.y; acc.z += bb.z; acc.w += bb.w;
    if (LAYER == 1) {
        acc.x = fmaxf(acc.x, 0.f); acc.y = fmaxf(acc.y, 0.f);
        acc.z = fmaxf(acc.z, 0.f); acc.w = fmaxf(acc.w, 0.f);
        uint32_t l0, l1;
        uint32_t h0 = pk2(acc.x, acc.y, l0);
        uint32_t h1 = pk2(acc.z, acc.w, l1);
        ((uint2*)g_h1h)[(size_t)w * 32 + lane] = make_uint2(h0, h1);
        ((uint2*)g_h1l)[(size_t)w * 32 + lane] = make_uint2(l0, l1);
    } else {
        uint32_t l0, l1;
        uint32_t h0 = pk2(acc.x, acc.y, l0);
        uint32_t h1 = pk2(acc.z, acc.w, l1);
        uint2 hi2 = make_uint2(h0, h1), lo2 = make_uint2(l0, l1);
        ((uint2*)g_cbh)[(size_t)w * 64 + lane] = hi2;
        ((uint2*)g_cbl)[(size_t)w * 64 + lane] = lo2;
        ((uint2*)g_c2h)[(size_t)w * 64 + lane] = hi2;
        ((uint2*)g_c2l)[(size_t)w * 64 + lane] = lo2;
        float4 hv = ((const float4*)h)[(size_t)w * 32 + lane];
        uint32_t m0, m1;
        uint32_t g0 = pk2(hv.x, hv.y, m0);
        uint32_t g1 = pk2(hv.z, hv.w, m1);
        ((uint2*)g_cbh)[(size_t)w * 64 + 32 + lane] = make_uint2(g0, g1);
        ((uint2*)g_cbl)[(size_t)w * 64 + 32 + lane] = make_uint2(m0, m1);
    }
}

// ---------------- launcher ----------------
extern "C" void kernel_launch(void* const* d_in, const int* in_sizes, int n_in,
                              void* d_out, int out_size) {
    const float* x     = (const float*)d_in[0];
    const float* h     = (const float*)d_in[1];
    const int*   edge  = (const int*)d_in[2];
    const float* W_in  = (const float*)d_in[3];
    const float* b_in  = (const float*)d_in[4];
    const float* W_hid = (const float*)d_in[5];
    const float* b_hid = (const float*)d_in[6];
    const float* W_z   = (const float*)d_in[7];
    const float* b_z   = (const float*)d_in[8];
    const float* W_r   = (const float*)d_in[9];
    const float* b_r   = (const float*)d_in[10];
    const float* W_c   = (const float*)d_in[11];
    const float* b_c   = (const float*)d_in[12];
    float* out = (float*)d_out;

    const int N = in_sizes[0] / 128;
    const int E = in_sizes[2] / 2;

    float *p_xw, *p_zr;
    __nv_bfloat16 *p_bh, *p_bl, *p_xh, *p_xl, *p_h1h, *p_h1l, *p_cbh, *p_cbl, *p_c2h, *p_c2l;
    cudaGetSymbolAddress((void**)&p_xw,  g_xw);
    cudaGetSymbolAddress((void**)&p_zr,  g_zr);
    cudaGetSymbolAddress((void**)&p_bh,  g_bthi);
    cudaGetSymbolAddress((void**)&p_bl,  g_btlo);
    cudaGetSymbolAddress((void**)&p_xh,  g_xh);
    cudaGetSymbolAddress((void**)&p_xl,  g_xl);
    cudaGetSymbolAddress((void**)&p_h1h, g_h1h);
    cudaGetSymbolAddress((void**)&p_h1l, g_h1l);
    cudaGetSymbolAddress((void**)&p_cbh, g_cbh);
    cudaGetSymbolAddress((void**)&p_cbl, g_cbl);
    cudaGetSymbolAddress((void**)&p_c2h, g_c2h);
    cudaGetSymbolAddress((void**)&p_c2l, g_c2l);

    cudaFuncSetAttribute(k_gemm3<0>, cudaFuncAttributeMaxDynamicSharedMemorySize, GSMEM);
    cudaFuncSetAttribute(k_gemm3<2>, cudaFuncAttributeMaxDynamicSharedMemorySize, GSMEM);
    cudaFuncSetAttribute(k_gemm3<3>, cudaFuncAttributeMaxDynamicSharedMemorySize, GSMEM);

    const int T = 256;
    const int mtiles = (N + 127) / 128;
    dim3 g1(mtiles, 1), g2(mtiles, 2);
    const int aggB = (NN + 7) / 8;

    // CSR build + dinv
    k_zero_cnt<<<(NN + T - 1) / T, T>>>();
    k_hist<<<(E + T - 1) / T, T>>>(edge + E, E);
    k_scan_block<<<NB, 256>>>();
    k_scan_top<<<1, 256>>>();
    k_scan_fin<<<(NN + T - 1) / T, T>>>(E);
    k_scatter<<<(E + T - 1) / T, T>>>(edge, E);

    k_prep_all<<<512, 256>>>(W_in, W_hid, W_z, W_r, W_c);
    k_split_x<<<(NN * 32 + T - 1) / T, T>>>(x);

    // layer 1
    k_gemm3<0><<<g1, T, GSMEM>>>(p_xh, p_xl, p_bh, p_bl, N, 128,
                                 p_xw, nullptr, nullptr, nullptr,
                                 nullptr, nullptr, nullptr, nullptr);
    k_agg_csr<1><<<aggB, T>>>(b_in, nullptr);

    // layer 2
    k_gemm3<0><<<g1, T, GSMEM>>>(p_h1h, p_h1l, p_bh + 16384, p_bl + 16384, N, 128,
                                 p_xw, nullptr, nullptr, nullptr,
                                 nullptr, nullptr, nullptr, nullptr);
    k_agg_csr<2><<<aggB, T>>>(b_hid, h);

    // gates: [z_pre | r] = comb @ [Wz|Wr]; r-half -> comb2 upper (split bf16)
    k_gemm3<3><<<g2, T, GSMEM>>>(p_cbh, p_cbl, p_bh + 32768, p_bl + 32768, N, 256,
                                 nullptr, p_zr, p_c2h, p_c2l,
                                 h, b_r, nullptr, nullptr);

    // out = (1-u)*h + u*tanh(comb2@Wc + b_c)
    k_gemm3<2><<<g1, T, GSMEM>>>(p_c2h, p_c2l, p_bh + 98304, p_bl + 98304, N, 256,
                                 out, nullptr, nullptr, nullptr,
                                 p_zr, h, b_z, b_c);
}

// round 6
// speedup vs baseline: 2.6561x; 1.1136x over previous
#include <cuda_runtime.h>
#include <cuda_bf16.h>
#include <cstdint>

#define NN 50000
#define NB ((NN + 255) / 256)   // 196

// ---------------- scratch ----------------
__device__ __align__(16) float g_deg[NN];
__device__ __align__(16) int   g_cnt[NN];
__device__ __align__(16) int   g_rowptr[NN + 1];
__device__ __align__(16) int   g_cursor[NN];
__device__ __align__(16) int   g_bsum[256];
__device__ __align__(16) int   g_csrsrc[600000];
__device__ __align__(16) float g_xw[(size_t)NN * 128];
__device__ __align__(16) float g_zr[(size_t)NN * 128];
__device__ __align__(16) __nv_bfloat16 g_xh[(size_t)NN * 128],  g_xl[(size_t)NN * 128];
__device__ __align__(16) __nv_bfloat16 g_h1h[(size_t)NN * 128], g_h1l[(size_t)NN * 128];
__device__ __align__(16) __nv_bfloat16 g_cbh[(size_t)NN * 256], g_cbl[(size_t)NN * 256];
__device__ __align__(16) __nv_bfloat16 g_c2h[(size_t)NN * 256], g_c2l[(size_t)NN * 256];
__device__ __align__(16) __nv_bfloat16 g_bthi[131072], g_btlo[131072];

__device__ __forceinline__ float sigmoidf_(float x) { return 1.0f / (1.0f + __expf(-x)); }

__device__ __forceinline__ uint32_t smem_u32(const void* p) {
    uint32_t a;
    asm("{ .reg .u64 t; cvta.to.shared.u64 t, %1; cvt.u32.u64 %0, t; }" : "=r"(a) : "l"(p));
    return a;
}
__device__ __forceinline__ void ldsm4(uint32_t& r0, uint32_t& r1, uint32_t& r2, uint32_t& r3,
                                      uint32_t addr) {
    asm volatile("ldmatrix.sync.aligned.m8n8.x4.shared.b16 {%0,%1,%2,%3}, [%4];"
                 : "=r"(r0), "=r"(r1), "=r"(r2), "=r"(r3) : "r"(addr));
}
__device__ __forceinline__ void mma16816(float* d, const uint32_t* a, uint32_t b0, uint32_t b1) {
    asm volatile(
        "mma.sync.aligned.m16n8k16.row.col.f32.bf16.bf16.f32 "
        "{%0,%1,%2,%3}, {%4,%5,%6,%7}, {%8,%9}, {%0,%1,%2,%3};"
        : "+f"(d[0]), "+f"(d[1]), "+f"(d[2]), "+f"(d[3])
        : "r"(a[0]), "r"(a[1]), "r"(a[2]), "r"(a[3]), "r"(b0), "r"(b1));
}
__device__ __forceinline__ uint32_t pk2(float x, float y, uint32_t& lo2) {
    __nv_bfloat16 hx = __float2bfloat16(x), hy = __float2bfloat16(y);
    __nv_bfloat16 lx = __float2bfloat16(x - __bfloat162float(hx));
    __nv_bfloat16 ly = __float2bfloat16(y - __bfloat162float(hy));
    lo2 = ((uint32_t)__bfloat16_as_ushort(ly) << 16) | __bfloat16_as_ushort(lx);
    return ((uint32_t)__bfloat16_as_ushort(hy) << 16) | __bfloat16_as_ushort(hx);
}

// ---------------- fused setup: zero cnt + weight split + x split ----------------
__global__ void k_setup(const float* __restrict__ x,
                        const float* __restrict__ Win, const float* __restrict__ Whid,
                        const float* __restrict__ Wz, const float* __restrict__ Wr,
                        const float* __restrict__ Wc) {
    int idx = blockIdx.x * blockDim.x + threadIdx.x;
    if (idx < NN) g_cnt[idx] = 0;
    if (idx < 131072) {
        float v; int dst;
        if (idx < 16384) {
            int k = idx >> 7, n = idx & 127;
            v = Win[idx]; dst = n * 128 + k;
        } else if (idx < 32768) {
            int i2 = idx - 16384; int k = i2 >> 7, n = i2 & 127;
            v = Whid[i2]; dst = 16384 + n * 128 + k;
        } else if (idx < 65536) {
            int i2 = idx - 32768; int k = i2 >> 7, n = i2 & 127;
            v = Wz[i2]; dst = 32768 + n * 256 + k;
        } else if (idx < 98304) {
            int i2 = idx - 65536; int k = i2 >> 7, n = i2 & 127;
            v = Wr[i2]; dst = 32768 + (128 + n) * 256 + k;
        } else {
            int i2 = idx - 98304; int k = i2 >> 7, n = i2 & 127;
            v = Wc[i2]; dst = 98304 + n * 256 + k;
        }
        __nv_bfloat16 hi = __float2bfloat16(v);
        __nv_bfloat16 lo = __float2bfloat16(v - __bfloat162float(hi));
        g_bthi[dst] = hi;
        g_btlo[dst] = lo;
    }
    if (idx < NN * 32) {
        float4 v = ((const float4*)x)[idx];
        uint32_t l0, l1;
        uint32_t h0 = pk2(v.x, v.y, l0);
        uint32_t h1 = pk2(v.z, v.w, l1);
        ((uint2*)g_xh)[idx] = make_uint2(h0, h1);
        ((uint2*)g_xl)[idx] = make_uint2(l0, l1);
    }
}

// ---------------- CSR build ----------------
__global__ void k_hist(const int* __restrict__ dst, int E) {
    int i = blockIdx.x * blockDim.x + threadIdx.x;
    if (i < E) atomicAdd(&g_cnt[dst[i]], 1);
}
__global__ void k_scan_block() {
    __shared__ int sh[256];
    int tid = threadIdx.x;
    int i = blockIdx.x * 256 + tid;
    int v = (i < NN) ? g_cnt[i] : 0;
    sh[tid] = v;
    __syncthreads();
#pragma unroll
    for (int off = 1; off < 256; off <<= 1) {
        int t = (tid >= off) ? sh[tid - off] : 0;
        __syncthreads();
        sh[tid] += t;
        __syncthreads();
    }
    if (i < NN) g_rowptr[i] = sh[tid] - v;
    if (tid == 255) g_bsum[blockIdx.x] = sh[255];
}
// merged: top-level scan (redundant per block) + finalize
__global__ void k_scan_fin(int E) {
    __shared__ int sh[256];
    int tid = threadIdx.x;
    int v = (tid < NB) ? g_bsum[tid] : 0;
    sh[tid] = v;
    __syncthreads();
#pragma unroll
    for (int off = 1; off < 256; off <<= 1) {
        int t = (tid >= off) ? sh[tid - off] : 0;
        __syncthreads();
        sh[tid] += t;
        __syncthreads();
    }
    __shared__ int s_off;
    if (tid == 0) s_off = sh[blockIdx.x] - g_bsum[blockIdx.x];  // exclusive prefix for this block
    __syncthreads();
    int i = blockIdx.x * 256 + tid;
    if (i >= NN) return;
    int r = g_rowptr[i] + s_off;
    g_rowptr[i] = r;
    g_cursor[i] = r;
    g_deg[i] = rsqrtf((float)(g_cnt[i] + 1));
    if (i == NN - 1) g_rowptr[NN] = E;
}
__global__ void k_scatter(const int* __restrict__ edge, int E) {
    int i = blockIdx.x * blockDim.x + threadIdx.x;
    if (i >= E) return;
    int d = edge[E + i];
    int pos = atomicAdd(&g_cursor[d], 1);
    g_csrsrc[pos] = edge[i];
}

// ---------------- HMMA GEMM: 64x128 tile, pre-split planes, cp.async 2-stage ----------------
#define PLA 5120             // 64 * 80
#define PLB 10240            // 128 * 80
#define BUFS (2 * PLA + 2 * PLB)   // 30720
#define GSMEM (2 * BUFS)           // 61440
#define AHI_O 0
#define ALO_O PLA
#define BHI_O (2 * PLA)
#define BLO_O (2 * PLA + PLB)

template <int MODE>
__global__ __launch_bounds__(256, 3) void k_gemm64(
    const __nv_bfloat16* __restrict__ Ah, const __nv_bfloat16* __restrict__ Al,
    const __nv_bfloat16* __restrict__ Bh, const __nv_bfloat16* __restrict__ Bl,
    int M, int K,
    float* __restrict__ C, float* __restrict__ zr,
    __nv_bfloat16* __restrict__ c2h, __nv_bfloat16* __restrict__ c2l,
    const float* __restrict__ p0, const float* __restrict__ p1,
    const float* __restrict__ p2, const float* __restrict__ p3)
{
    extern __shared__ char smem[];
    uint32_t sb = smem_u32(smem);
    int tid = threadIdx.x, lane = tid & 31, wid = tid >> 5;
    int wm = (wid >> 2) * 32, wn = (wid & 3) * 32;
    int bm = blockIdx.x * 64, bn = blockIdx.y * 128;

    float acc[2][4][4];
#pragma unroll
    for (int i = 0; i < 2; i++)
#pragma unroll
        for (int j = 0; j < 4; j++)
#pragma unroll
            for (int t = 0; t < 4; t++) acc[i][j][t] = 0.f;

    uint32_t aRow = lane & 15;
    uint32_t aK   = (lane >> 1) & 8;
    uint32_t bRow = (lane & 7) + ((lane >> 4) & 1) * 8;
    uint32_t bK   = ((lane >> 3) & 1) * 8;

    int arow = tid >> 2, aseg = tid & 3;

    auto load_chunk = [&](int buf, int c) {
        int k0 = c << 5;
        uint32_t bufb = sb + buf * BUFS;
        // A planes: 64 rows x 4 segs, 1 op/thread/plane
        int gra = min(bm + arow, M - 1);
        {
            const __nv_bfloat16* src = Ah + (size_t)gra * K + k0 + aseg * 8;
            uint32_t dst = bufb + AHI_O + arow * 80 + aseg * 16;
            asm volatile("cp.async.cg.shared.global [%0], [%1], 16;" :: "r"(dst), "l"(src));
        }
        {
            const __nv_bfloat16* src = Al + (size_t)gra * K + k0 + aseg * 8;
            uint32_t dst = bufb + ALO_O + arow * 80 + aseg * 16;
            asm volatile("cp.async.cg.shared.global [%0], [%1], 16;" :: "r"(dst), "l"(src));
        }
        // B planes: 128 rows x 4 segs, 2 ops/thread/plane
#pragma unroll
        for (int it = 0; it < 2; it++) {
            int i = tid + it * 256;
            int row = i >> 2, seg = i & 3;
            const __nv_bfloat16* srch = Bh + (size_t)(bn + row) * K + k0 + seg * 8;
            const __nv_bfloat16* srcl = Bl + (size_t)(bn + row) * K + k0 + seg * 8;
            uint32_t dsth = bufb + BHI_O + row * 80 + seg * 16;
            uint32_t dstl = bufb + BLO_O + row * 80 + seg * 16;
            asm volatile("cp.async.cg.shared.global [%0], [%1], 16;" :: "r"(dsth), "l"(srch));
            asm volatile("cp.async.cg.shared.global [%0], [%1], 16;" :: "r"(dstl), "l"(srcl));
        }
        asm volatile("cp.async.commit_group;" ::: "memory");
    };

    auto compute_chunk = [&](int buf) {
        uint32_t base = sb + buf * BUFS;
#pragma unroll
        for (int ks = 0; ks < 2; ks++) {
            uint32_t ah[2][4], al[2][4];
#pragma unroll
            for (int mt = 0; mt < 2; mt++) {
                uint32_t ao = base + AHI_O + (wm + mt * 16 + aRow) * 80 + (ks * 16 + aK) * 2;
                ldsm4(ah[mt][0], ah[mt][1], ah[mt][2], ah[mt][3], ao);
                ldsm4(al[mt][0], al[mt][1], al[mt][2], al[mt][3], ao + (ALO_O - AHI_O));
            }
#pragma unroll
            for (int np = 0; np < 2; np++) {
                uint32_t bo = base + BHI_O + (wn + np * 16 + bRow) * 80 + (ks * 16 + bK) * 2;
                uint32_t bh[4], bl[4];
                ldsm4(bh[0], bh[1], bh[2], bh[3], bo);
                ldsm4(bl[0], bl[1], bl[2], bl[3], bo + (BLO_O - BHI_O));
#pragma unroll
                for (int mt = 0; mt < 2; mt++) {
                    mma16816(acc[mt][np * 2],     ah[mt], bh[0], bh[1]);
                    mma16816(acc[mt][np * 2],     ah[mt], bl[0], bl[1]);
                    mma16816(acc[mt][np * 2],     al[mt], bh[0], bh[1]);
                    mma16816(acc[mt][np * 2 + 1], ah[mt], bh[2], bh[3]);
                    mma16816(acc[mt][np * 2 + 1], ah[mt], bl[2], bl[3]);
                    mma16816(acc[mt][np * 2 + 1], al[mt], bh[2], bh[3]);
                }
            }
        }
    };

    int nc = K >> 5;
    load_chunk(0, 0);
    for (int c = 0; c < nc; c++) {
        if (c + 1 < nc) {
            load_chunk((c + 1) & 1, c + 1);
            asm volatile("cp.async.wait_group 1;" ::: "memory");
        } else {
            asm volatile("cp.async.wait_group 0;" ::: "memory");
        }
        __syncthreads();
        compute_chunk(c & 1);
        __syncthreads();
    }

    // ---------------- epilogue ----------------
#pragma unroll
    for (int mt = 0; mt < 2; mt++)
#pragma unroll
        for (int nt = 0; nt < 4; nt++) {
            int colg = bn + wn + nt * 8 + ((lane & 3) << 1);
            int rbase = bm + wm + mt * 16 + (lane >> 2);
#pragma unroll
            for (int half = 0; half < 2; half++) {
                int row = rbase + half * 8;
                if (row >= M) continue;
                float vx = acc[mt][nt][half * 2];
                float vy = acc[mt][nt][half * 2 + 1];
                if (MODE == 0) {
                    *(float2*)&C[(size_t)row * 128 + colg] = make_float2(vx, vy);
                } else if (MODE == 3) {
                    if (colg < 128) {
                        *(float2*)&zr[(size_t)row * 128 + colg] = make_float2(vx, vy);
                    } else {
                        int cc = colg - 128;
                        float2 hv = *(const float2*)&p0[(size_t)row * 128 + cc];
                        float2 bb = *(const float2*)&p1[cc];
                        float rx = sigmoidf_(vx + bb.x) * hv.x;
                        float ry = sigmoidf_(vy + bb.y) * hv.y;
                        uint32_t lo;
                        uint32_t hi = pk2(rx, ry, lo);
                        size_t idx = ((size_t)row * 256 + 128 + cc) >> 1;
                        ((uint32_t*)c2h)[idx] = hi;
                        ((uint32_t*)c2l)[idx] = lo;
                    }
                } else {  // MODE 2
                    size_t base = (size_t)row * 128 + colg;
                    float2 zp = *(const float2*)&p0[base];
                    float2 hv = *(const float2*)&p1[base];
                    float2 vbz = *(const float2*)&p2[colg];
                    float2 vbc = *(const float2*)&p3[colg];
                    float u0 = sigmoidf_(zp.x + vbz.x);
                    float u1 = sigmoidf_(zp.y + vbz.y);
                    float c0 = tanhf(vx + vbc.x);
                    float c1 = tanhf(vy + vbc.y);
                    *(float2*)&C[base] = make_float2((1.f - u0) * hv.x + u0 * c0,
                                                     (1.f - u1) * hv.y + u1 * c1);
                }
            }
        }
}

// ---------------- CSR aggregation: warp per dst node ----------------
template <int LAYER>
__global__ __launch_bounds__(256) void k_agg_csr(const float* __restrict__ b,
                                                 const float* __restrict__ h) {
    int w = blockIdx.x * 8 + (threadIdx.x >> 5);
    if (w >= NN) return;
    int lane = threadIdx.x & 31;
    const float4* xw4 = (const float4*)g_xw;

    float dd = g_deg[w];
    float4 acc = xw4[(size_t)w * 32 + lane];
    float cself = dd * dd;
    acc.x *= cself; acc.y *= cself; acc.z *= cself; acc.w *= cself;

    int start = g_rowptr[w], end = g_rowptr[w + 1];
    for (int base = start; base < end; base += 32) {
        int e = base + lane;
        int sv = 0; float dv = 0.f;
        if (e < end) { sv = g_csrsrc[e]; dv = g_deg[sv]; }
        int cnt = end - base; if (cnt > 32) cnt = 32;
        for (int j = 0; j < cnt; j++) {
            int s = __shfl_sync(0xffffffffu, sv, j);
            float c = __shfl_sync(0xffffffffu, dv, j) * dd;
            float4 v = xw4[(size_t)s * 32 + lane];
            acc.x += v.x * c; acc.y += v.y * c; acc.z += v.z * c; acc.w += v.w * c;
        }
    }

    float4 bb = *(const float4*)&b[lane * 4];
    acc.x += bb.x; acc.y += bb.y; acc.z += bb.z; acc.w += bb.w;
    if (LAYER == 1) {
        acc.x = fmaxf(acc.x, 0.f); acc.y = fmaxf(acc.y, 0.f);
        acc.z = fmaxf(acc.z, 0.f); acc.w = fmaxf(acc.w, 0.f);
        uint32_t l0, l1;
        uint32_t h0 = pk2(acc.x, acc.y, l0);
        uint32_t h1 = pk2(acc.z, acc.w, l1);
        ((uint2*)g_h1h)[(size_t)w * 32 + lane] = make_uint2(h0, h1);
        ((uint2*)g_h1l)[(size_t)w * 32 + lane] = make_uint2(l0, l1);
    } else {
        uint32_t l0, l1;
        uint32_t h0 = pk2(acc.x, acc.y, l0);
        uint32_t h1 = pk2(acc.z, acc.w, l1);
        uint2 hi2 = make_uint2(h0, h1), lo2 = make_uint2(l0, l1);
        ((uint2*)g_cbh)[(size_t)w * 64 + lane] = hi2;
        ((uint2*)g_cbl)[(size_t)w * 64 + lane] = lo2;
        ((uint2*)g_c2h)[(size_t)w * 64 + lane] = hi2;
        ((uint2*)g_c2l)[(size_t)w * 64 + lane] = lo2;
        float4 hv = ((const float4*)h)[(size_t)w * 32 + lane];
        uint32_t m0, m1;
        uint32_t g0 = pk2(hv.x, hv.y, m0);
        uint32_t g1 = pk2(hv.z, hv.w, m1);
        ((uint2*)g_cbh)[(size_t)w * 64 + 32 + lane] = make_uint2(g0, g1);
        ((uint2*)g_cbl)[(size_t)w * 64 + 32 + lane] = make_uint2(m0, m1);
    }
}

// ---------------- launcher ----------------
extern "C" void kernel_launch(void* const* d_in, const int* in_sizes, int n_in,
                              void* d_out, int out_size) {
    const float* x     = (const float*)d_in[0];
    const float* h     = (const float*)d_in[1];
    const int*   edge  = (const int*)d_in[2];
    const float* W_in  = (const float*)d_in[3];
    const float* b_in  = (const float*)d_in[4];
    const float* W_hid = (const float*)d_in[5];
    const float* b_hid = (const float*)d_in[6];
    const float* W_z   = (const float*)d_in[7];
    const float* b_z   = (const float*)d_in[8];
    const float* W_r   = (const float*)d_in[9];
    const float* b_r   = (const float*)d_in[10];
    const float* W_c   = (const float*)d_in[11];
    const float* b_c   = (const float*)d_in[12];
    float* out = (float*)d_out;

    const int N = in_sizes[0] / 128;
    const int E = in_sizes[2] / 2;

    float *p_xw, *p_zr;
    __nv_bfloat16 *p_bh, *p_bl, *p_xh, *p_xl, *p_h1h, *p_h1l, *p_cbh, *p_cbl, *p_c2h, *p_c2l;
    cudaGetSymbolAddress((void**)&p_xw,  g_xw);
    cudaGetSymbolAddress((void**)&p_zr,  g_zr);
    cudaGetSymbolAddress((void**)&p_bh,  g_bthi);
    cudaGetSymbolAddress((void**)&p_bl,  g_btlo);
    cudaGetSymbolAddress((void**)&p_xh,  g_xh);
    cudaGetSymbolAddress((void**)&p_xl,  g_xl);
    cudaGetSymbolAddress((void**)&p_h1h, g_h1h);
    cudaGetSymbolAddress((void**)&p_h1l, g_h1l);
    cudaGetSymbolAddress((void**)&p_cbh, g_cbh);
    cudaGetSymbolAddress((void**)&p_cbl, g_cbl);
    cudaGetSymbolAddress((void**)&p_c2h, g_c2h);
    cudaGetSymbolAddress((void**)&p_c2l, g_c2l);

    cudaFuncSetAttribute(k_gemm64<0>, cudaFuncAttributeMaxDynamicSharedMemorySize, GSMEM);
    cudaFuncSetAttribute(k_gemm64<2>, cudaFuncAttributeMaxDynamicSharedMemorySize, GSMEM);
    cudaFuncSetAttribute(k_gemm64<3>, cudaFuncAttributeMaxDynamicSharedMemorySize, GSMEM);

    // side stream + events for capture-fork (created on the uncaptured correctness call)
    static cudaStream_t s1 = nullptr;
    static cudaEvent_t evA = nullptr, evB = nullptr;
    static bool tried = false;
    if (!tried) {
        tried = true;
        if (cudaStreamCreateWithFlags(&s1, cudaStreamNonBlocking) != cudaSuccess) s1 = nullptr;
        if (s1) {
            if (cudaEventCreateWithFlags(&evA, cudaEventDisableTiming) != cudaSuccess) evA = nullptr;
            if (cudaEventCreateWithFlags(&evB, cudaEventDisableTiming) != cudaSuccess) evB = nullptr;
            if (!evA || !evB) s1 = nullptr;
        }
    }
    cudaStream_t sCsr = s1 ? s1 : (cudaStream_t)0;
    bool fork = (s1 != nullptr);

    const int T = 256;
    const int mt64 = (N + 63) / 64;       // 782
    dim3 g1(mt64, 1), g2(mt64, 2);
    const int aggB = (NN + 7) / 8;

    // setup (stream 0): zero cnt + weight split + x split
    k_setup<<<(NN * 32 + T - 1) / T, T>>>(x, W_in, W_hid, W_z, W_r, W_c);

    if (fork) cudaEventRecord(evA, 0);
    if (fork) cudaStreamWaitEvent(sCsr, evA, 0);

    // CSR chain (side stream when available)
    k_hist<<<(E + T - 1) / T, T, 0, sCsr>>>(edge + E, E);
    k_scan_block<<<NB, 256, 0, sCsr>>>();
    k_scan_fin<<<NB, 256, 0, sCsr>>>(E);
    k_scatter<<<(E + T - 1) / T, T, 0, sCsr>>>(edge, E);
    if (fork) cudaEventRecord(evB, sCsr);

    // GEMM1 on stream 0, overlapped with CSR build
    k_gemm64<0><<<g1, T, GSMEM>>>(p_xh, p_xl, p_bh, p_bl, N, 128,
                                  p_xw, nullptr, nullptr, nullptr,
                                  nullptr, nullptr, nullptr, nullptr);
    if (fork) cudaStreamWaitEvent((cudaStream_t)0, evB, 0);

    k_agg_csr<1><<<aggB, T>>>(b_in, nullptr);

    k_gemm64<0><<<g1, T, GSMEM>>>(p_h1h, p_h1l, p_bh + 16384, p_bl + 16384, N, 128,
                                  p_xw, nullptr, nullptr, nullptr,
                                  nullptr, nullptr, nullptr, nullptr);
    k_agg_csr<2><<<aggB, T>>>(b_hid, h);

    // gates: [z_pre | r] = comb @ [Wz|Wr]; r-half -> comb2 upper
    k_gemm64<3><<<g2, T, GSMEM>>>(p_cbh, p_cbl, p_bh + 32768, p_bl + 32768, N, 256,
                                  nullptr, p_zr, p_c2h, p_c2l,
                                  h, b_r, nullptr, nullptr);

    // out = (1-u)*h + u*tanh(comb2@Wc + b_c)
    k_gemm64<2><<<g1, T, GSMEM>>>(p_c2h, p_c2l, p_bh + 98304, p_bl + 98304, N, 256,
                                  out, nullptr, nullptr, nullptr,
                                  p_zr, h, b_z, b_c);
}